// round 10
// baseline (speedup 1.0000x reference)
#include <cuda_runtime.h>

typedef unsigned long long u64;

#define B_  512
#define T_  512
#define F_  13
#define H_  128
#define NT  512

// 134MB scratch: xp[(b*T + t)*H + j] = x@W_ih^T + b_ih + b_hh
__device__ float g_xp[(size_t)B_ * T_ * H_];

__device__ __forceinline__ u64 fma2(u64 a, u64 b, u64 c) {
    u64 d;
    asm("fma.rn.f32x2 %0, %1, %2, %3;" : "=l"(d) : "l"(a), "l"(b), "l"(c));
    return d;
}
__device__ __forceinline__ float f2sum(u64 a) {
    float lo, hi;
    asm("mov.b64 {%0, %1}, %2;" : "=f"(lo), "=f"(hi) : "l"(a));
    return lo + hi;
}
// tanh(x) = 1 - 2/(1+e^{2x}); abs err ~1e-7, inf-safe.
__device__ __forceinline__ float tanh_fast(float x) {
    float e = __expf(2.f * x);
    return 1.f - __fdividef(2.f, 1.f + e);
}
__device__ __forceinline__ float sigmoid_fast(float s) {
    return __fdividef(1.f, 1.f + __expf(-s));
}

// ---------------------------------------------------------------------------
// Kernel 1: xp precompute (validated in R9). 256 threads / 256 (b,t) rows.
// ---------------------------------------------------------------------------
__global__ void __launch_bounds__(256, 2) xp_kernel(
    const float* __restrict__ x,
    const float* __restrict__ W_ih,
    const float* __restrict__ b_ih,
    const float* __restrict__ b_hh)
{
    __shared__ float xs[256 * 14];
    const int tid = threadIdx.x;
    const size_t rowbase = (size_t)blockIdx.x * 256;

    for (int i = tid; i < 256 * F_; i += 256) {
        int r = i / F_, f = i - r * F_;
        xs[r * 14 + f] = x[rowbase * F_ + i];
    }
    __syncthreads();

    const int j    = tid & 127;
    const int half = tid >> 7;
    float w[F_];
#pragma unroll
    for (int f = 0; f < F_; f++) w[f] = __ldg(W_ih + j * F_ + f);
    const float bias = __ldg(b_ih + j) + __ldg(b_hh + j);

    const int r0 = half * 128;
    for (int r = 0; r < 128; r++) {
        const float* xr = xs + (r0 + r) * 14;
        float acc = bias;
#pragma unroll
        for (int f = 0; f < F_; f++) acc = fmaf(xr[f], w[f], acc);
        g_xp[(rowbase + r0 + r) * H_ + j] = acc;
    }
}

// ---------------------------------------------------------------------------
// Kernel 2: fused persistent scan + fc head.
// 128 CTAs x 512 threads (4 warps/SMSP), 4 batch rows per CTA,
// ONE __syncthreads per step, <=128 regs/thread by construction.
//
// Rec (tid 0..255, warps 0-7): thread (jj = tid>>1, kh = tid&1) holds ONE
//   W_hh row k-half: W_hh[jj][64kh : 64kh+64) -> 64 f32 regs. Partial dots
//   for all 4 rows over its k-half (128 fma2). Partner lane^1 has the other
//   k-half of the same jj: shfl_xor(1) swaps cross partials. Adds staged
//   xp from Xp[cur], tanh, stores its 2 rows {2kh, 2kh+1} into Hs[cur^1].
//   NO global loads in the loop.
// FC (tid 256..511, warps 8-15): thread (o = ft>>2, q = ft&3) holds a
//   QUARTER fc1 row: fc1_w[o][32q : 32q+32) -> 32 regs. Quarter dots on
//   h(t) = Hs[cur] for all 4 rows (64 fma2); shfl_xor(1),(2) merge quarters;
//   relu*fc2_w; shfl_xor(4,8,16) reduce the warp's 8 o's; lane0 ->
//   red[cur^1][warp][4]. Separately stages xp(t+1) (2 coalesced LDG + STS)
//   into Xp[cur^1]. 4 threads emit sigmoid+STG one iteration later.
// ---------------------------------------------------------------------------
__global__ void __launch_bounds__(NT, 1) rnn_fused(
    const float* __restrict__ W_hh,
    const float* __restrict__ fc1_w,
    const float* __restrict__ fc1_b,
    const float* __restrict__ fc2_w,
    const float* __restrict__ fc2_b,
    float* __restrict__ out)
{
    __shared__ __align__(16) float Hs[2][4 * H_];   // double-buffered h
    __shared__ __align__(16) float Xp[2][4 * H_];   // double-buffered xp tile
    __shared__ float red[2][8][4];                  // [buf][fc warp][row]

    const int tid  = threadIdx.x;
    const int row0 = blockIdx.x * 4;

    // ---- init: zero h(0), stage xp(0) ----
    {
        const int r = tid >> 7, j = tid & 127;
        Hs[0][tid & 511] = 0.f;                 // tid<512 covers 4*128 floats... (see below)
        // (Hs[0] has 512 floats; each thread zeroes exactly one.)
        Xp[0][r * H_ + j] = g_xp[((size_t)(row0 + r) * T_) * H_ + j];
    }
    __syncthreads();

    int cur = 0;

    if (tid < 256) {
        // =================== RECURRENCE ===================
        const int jj   = tid >> 1;       // 0..127
        const int kh   = tid & 1;        // k-half
        const int koff = kh * 64;
        const int r0   = 2 * kh,     r1 = 2 * kh + 1;   // rows finalized here
        const int o0   = 2 - 2 * kh, o1 = 3 - 2 * kh;   // partner's rows

        u64 w[32];   // 64 floats: W_hh[jj][koff .. koff+64)
        {
            const ulonglong2* wrow =
                (const ulonglong2*)(W_hh + (size_t)jj * H_ + koff);
#pragma unroll
            for (int m = 0; m < 16; m++) {
                ulonglong2 v = wrow[m];
                w[2 * m] = v.x; w[2 * m + 1] = v.y;
            }
        }

        for (int t = 0; t < T_; t++) {
            const float* Hrd = Hs[cur];
            float*       Hwr = Hs[cur ^ 1];
            const float* Xr  = Xp[cur];

            u64 a0[4], a1[4];
#pragma unroll
            for (int r = 0; r < 4; r++) { a0[r] = 0ull; a1[r] = 0ull; }

#pragma unroll
            for (int m = 0; m < 16; m++) {
                ulonglong2 h0 = *(const ulonglong2*)(Hrd + 0 * H_ + koff + 4 * m);
                ulonglong2 h1 = *(const ulonglong2*)(Hrd + 1 * H_ + koff + 4 * m);
                ulonglong2 h2 = *(const ulonglong2*)(Hrd + 2 * H_ + koff + 4 * m);
                ulonglong2 h3 = *(const ulonglong2*)(Hrd + 3 * H_ + koff + 4 * m);
                a0[0] = fma2(h0.x, w[2 * m], a0[0]);
                a0[1] = fma2(h1.x, w[2 * m], a0[1]);
                a0[2] = fma2(h2.x, w[2 * m], a0[2]);
                a0[3] = fma2(h3.x, w[2 * m], a0[3]);
                a1[0] = fma2(h0.y, w[2 * m + 1], a1[0]);
                a1[1] = fma2(h1.y, w[2 * m + 1], a1[1]);
                a1[2] = fma2(h2.y, w[2 * m + 1], a1[2]);
                a1[3] = fma2(h3.y, w[2 * m + 1], a1[3]);
            }

            float own_s0 = f2sum(a0[r0]) + f2sum(a1[r0]);
            float own_s1 = f2sum(a0[r1]) + f2sum(a1[r1]);
            float q0 = f2sum(a0[o0]) + f2sum(a1[o0]);
            float q1 = f2sum(a0[o1]) + f2sum(a1[o1]);
            // partner (lane^1) holds the other k-half of MY rows (symmetric)
            float e0 = __shfl_xor_sync(0xffffffffu, q0, 1);
            float e1 = __shfl_xor_sync(0xffffffffu, q1, 1);

            Hwr[r0 * H_ + jj] = tanh_fast(own_s0 + e0 + Xr[r0 * H_ + jj]);
            Hwr[r1 * H_ + jj] = tanh_fast(own_s1 + e1 + Xr[r1 * H_ + jj]);

            __syncthreads();
            cur ^= 1;
        }
        __syncthreads();    // pairs with fc's t = T_ iteration
    } else {
        // =================== FC HEAD + xp staging ===================
        const int ft   = tid - 256;      // 0..255
        const int o    = ft >> 2;        // 0..63
        const int q    = ft & 3;         // quarter
        const int wloc = ft >> 5;        // 0..7 (fc warp)
        const int lane = ft & 31;
        const int qoff = q * 32;

        u64 fw[16];  // 32 floats: fc1_w[o][qoff .. qoff+32)
        {
            const ulonglong2* fr =
                (const ulonglong2*)(fc1_w + (size_t)o * H_ + qoff);
#pragma unroll
            for (int m = 0; m < 8; m++) {
                ulonglong2 v = fr[m];
                fw[2 * m] = v.x; fw[2 * m + 1] = v.y;
            }
        }
        const float b1 = __ldg(fc1_b + o);
        const float w2 = __ldg(fc2_w + o);
        const float b2 = __ldg(fc2_b);

        // xp staging role: thread ft loads 2 floats (j = jx, jx+64) of row rx
        const int jx = ft & 63;
        const int rx = ft >> 6;
        const float* xsrc =
            g_xp + (((size_t)(row0 + rx) * T_) + 1) * H_ + jx;

        for (int t = 0; t <= T_; t++) {
            // emit out index t-2 (combined at iter t-1)
            if (t >= 2 && ft < 4) {
                const int r = ft;
                float s = b2;
#pragma unroll
                for (int wv = 0; wv < 8; wv++) s += red[cur][wv][r];
                out[(size_t)(row0 + r) * T_ + (t - 2)] = sigmoid_fast(s);
            }

            // stage xp(t+1) into Xp[cur^1] (consumed by rec at iter t+1)
            if (t + 1 < T_) {
                float v0 = __ldg(xsrc);
                float v1 = __ldg(xsrc + 64);
                Xp[cur ^ 1][rx * H_ + jx]      = v0;
                Xp[cur ^ 1][rx * H_ + jx + 64] = v1;
                xsrc += H_;
            }

            if (t >= 1) {
                const float* Hrd = Hs[cur];      // h(t)
                u64 c0[4], c1[4];
#pragma unroll
                for (int r = 0; r < 4; r++) { c0[r] = 0ull; c1[r] = 0ull; }
#pragma unroll
                for (int m = 0; m < 8; m++) {
#pragma unroll
                    for (int r = 0; r < 4; r++) {
                        ulonglong2 hv =
                            *(const ulonglong2*)(Hrd + r * H_ + qoff + 4 * m);
                        c0[r] = fma2(hv.x, fw[2 * m],     c0[r]);
                        c1[r] = fma2(hv.y, fw[2 * m + 1], c1[r]);
                    }
                }
                float y[4];
#pragma unroll
                for (int r = 0; r < 4; r++) {
                    float d = f2sum(c0[r]) + f2sum(c1[r]);
                    // merge quarters (lanes ^1, ^2 share the same o)
                    d += __shfl_xor_sync(0xffffffffu, d, 1);
                    d += __shfl_xor_sync(0xffffffffu, d, 2);
                    y[r] = fmaxf(d + b1, 0.f) * w2;
                }
                // reduce the warp's 8 distinct o's (each o's 4 q-lanes hold
                // identical copies; offsets 4,8,16 sum distinct o's once)
#pragma unroll
                for (int off = 4; off <= 16; off <<= 1) {
#pragma unroll
                    for (int r = 0; r < 4; r++)
                        y[r] += __shfl_xor_sync(0xffffffffu, y[r], off);
                }
                if (lane == 0) {
#pragma unroll
                    for (int r = 0; r < 4; r++) red[cur ^ 1][wloc][r] = y[r];
                }
            }

            __syncthreads();
            cur ^= 1;
        }

        // final output index T_-1 (combined at iter T_)
        if (ft < 4) {
            const int r = ft;
            float s = b2;
#pragma unroll
            for (int wv = 0; wv < 8; wv++) s += red[cur][wv][r];
            out[(size_t)(row0 + r) * T_ + (T_ - 1)] = sigmoid_fast(s);
        }
    }
}

// ---------------------------------------------------------------------------

extern "C" void kernel_launch(void* const* d_in, const int* in_sizes, int n_in,
                              void* d_out, int out_size)
{
    const float* x     = (const float*)d_in[0];
    const float* W_ih  = (const float*)d_in[1];
    const float* W_hh  = (const float*)d_in[2];
    const float* b_ih  = (const float*)d_in[3];
    const float* b_hh  = (const float*)d_in[4];
    const float* fc1_w = (const float*)d_in[5];
    const float* fc1_b = (const float*)d_in[6];
    const float* fc2_w = (const float*)d_in[7];
    const float* fc2_b = (const float*)d_in[8];
    float* out = (float*)d_out;

    xp_kernel<<<(B_ * T_) / 256, 256>>>(x, W_ih, b_ih, b_hh);
    rnn_fused<<<128, NT>>>(W_hh, fc1_w, fc1_b, fc2_w, fc2_b, out);
}